// round 13
// baseline (speedup 1.0000x reference)
#include <cuda_runtime.h>
#include <math.h>

#define NA   768
#define FDIM 128
#define NRBF 32
#define MAXNBR 192
#define MAXPAIRS (NA*MAXNBR)
#define CPCH 8                 /* pairs per chunk */
#define PGRID 2048             /* blocks for pair-parallel kernels */

// Physics constants (match reference exactly)
#define CUT2f   25.0f
#define GAMf    40.96f                       /* (32/5)^2 */
#define CSPf    (5.0f/31.0f)                 /* RBF center spacing */
#define KBf     8.617330337217213e-05f
#define KTf     (300.0f*KBf)
#define Q0f     (2.0f*(float)(NA*3)*KTf*400.0f)
#define QCf     (2.0f*KTf*400.0f)
#define TARGETf (0.5f*(float)(NA*3)*KTf)

typedef unsigned long long ull;

// packed fp32x2 helpers (Blackwell FFMA2 — PTX-only)
__device__ __forceinline__ void fma2(ull& d, ull a, ull b) {
    asm("fma.rn.f32x2 %0, %1, %2, %0;" : "+l"(d) : "l"(a), "l"(b));
}
__device__ __forceinline__ ull pk2(float lo, float hi) {
    ull r; asm("mov.b64 %0, {%1, %2};" : "=l"(r) : "f"(lo), "f"(hi)); return r;
}
__device__ __forceinline__ float hadd2(ull v) {
    float lo, hi; asm("mov.b64 {%0, %1}, %2;" : "=f"(lo), "=f"(hi) : "l"(v));
    return lo + hi;
}

// Scratch (static __device__ arrays: allocation-free, graph-safe)
__device__ int      g_nbr[NA*MAXNBR];
__device__ int      g_cnt[NA];
__device__ int      g_off[NA];
__device__ int      g_np;
__device__ int      g_pi[MAXPAIRS];
__device__ int      g_pj[MAXPAIRS];
__device__ float    g_h  [NA*FDIM];
__device__ float    g_W2T[FDIM*FDIM];
__device__ float    g_W3T[FDIM*FDIM];
__device__ float    g_m  [NA*FDIM];          // messages (atomic accumulation)
__device__ float    g_gm [NA*FDIM];          // dE/dm per atom
__device__ float    g_gq [NA*3];             // dE/dq accumulator
__device__ unsigned g_relu[MAXPAIRS*4];      // relu(z) mask bits per (pair, warp)

// ---------------------------------------------------------------------------
// K0: gather h, zero g_m, transpose W2/W3
__global__ void k_prep(const float* __restrict__ embed, const int* __restrict__ zat,
                       const float* __restrict__ W2, const float* __restrict__ W3) {
    int b = blockIdx.x, t = threadIdx.x;
    g_h[b*FDIM + t] = embed[zat[b]*FDIM + t];
    g_m[b*FDIM + t] = 0.0f;
    if (b < FDIM) {
        g_W2T[b*FDIM + t] = W2[t*FDIM + b];
        g_W3T[b*FDIM + t] = W3[t*FDIM + b];
    }
}

// ---------------------------------------------------------------------------
// K1: cutoff neighbor list (block per atom, q cached in smem) + zero forces
__global__ void k_nbr(const float* __restrict__ q) {
    __shared__ float sq[NA*3];
    __shared__ int cnt;
    int i = blockIdx.x, t = threadIdx.x;
    if (t == 0) cnt = 0;
    if (t < 3)  g_gq[i*3 + t] = 0.0f;
    for (int idx = t; idx < NA*3; idx += 256) sq[idx] = q[idx];
    __syncthreads();
    float qx = sq[3*i], qy = sq[3*i+1], qz = sq[3*i+2];
    for (int j = t; j < NA; j += 256) {
        if (j == i) continue;
        float dx = qx - sq[3*j], dy = qy - sq[3*j+1], dz = qz - sq[3*j+2];
        float d2 = dx*dx + dy*dy + dz*dz;
        if (d2 < CUT2f) {
            int p = atomicAdd(&cnt, 1);
            if (p < MAXNBR) g_nbr[i*MAXNBR + p] = j;
        }
    }
    __syncthreads();
    if (t == 0) g_cnt[i] = (cnt < MAXNBR) ? cnt : MAXNBR;
}

// ---------------------------------------------------------------------------
// K2: prefix-sum of per-atom counts (1 block, NA threads) -> offsets + total
__global__ void k_scan() {
    __shared__ int s[NA];
    int t = threadIdx.x;
    s[t] = g_cnt[t];
    __syncthreads();
    for (int off = 1; off < NA; off <<= 1) {
        int v = s[t];
        int add = (t >= off) ? s[t - off] : 0;
        __syncthreads();
        s[t] = v + add;
        __syncthreads();
    }
    g_off[t] = s[t] - g_cnt[t];
    if (t == NA - 1) g_np = s[t];
}

// K3: scatter per-atom lists into flat directed-pair arrays
__global__ void k_scat() {
    int i = blockIdx.x, t = threadIdx.x;
    int cnt = g_cnt[i], off = g_off[i];
    for (int s = t; s < cnt; s += blockDim.x) {
        g_pi[off + s] = i;
        g_pj[off + s] = g_nbr[i*MAXNBR + s];
    }
}

// ---------------------------------------------------------------------------
// K4: forward, pair-parallel. 128 threads per block, CPCH pairs per chunk,
// grid-stride over chunks. Weights read from L1-resident global (no smem W).
__global__ void __launch_bounds__(128)
k_fwdP(const float* __restrict__ q,  const float* __restrict__ W1,
       const float* __restrict__ b1, const float* __restrict__ b2) {
    __shared__ float rbf[CPCH*NRBF];
    __shared__ float sA [CPCH*FDIM];
    __shared__ int   sI[CPCH], sJ[CPCH];
    __shared__ float sVal[CPCH];
    int lt = threadIdx.x, warp = lt >> 5;
    int np = g_np;
    int nch = (np + CPCH - 1) / CPCH;
    float b1t = b1[lt], b2t = b2[lt];

    for (int c = blockIdx.x; c < nch; c += gridDim.x) {
        int pbase = c * CPCH;
        if (lt < CPCH) {
            int pidx = pbase + lt;
            bool v = pidx < np;
            sI[lt] = v ? g_pi[pidx] : 0;
            sJ[lt] = v ? g_pj[pidx] : 0;
            sVal[lt] = v ? 1.0f : 0.0f;
        }
        __syncthreads();
        {   // rbf: thread covers pair p = lt>>4, two k values
            int p = lt >> 4, kk = (lt & 15) * 2;
            int i = sI[p], j = sJ[p];
            float dx = q[3*i]-q[3*j], dy = q[3*i+1]-q[3*j+1], dz = q[3*i+2]-q[3*j+2];
            float d = sqrtf(dx*dx + dy*dy + dz*dz);
            float u0 = d - (float)kk*CSPf, u1 = d - (float)(kk+1)*CSPf;
            rbf[p*NRBF + kk]     = __expf(-GAMf*u0*u0);
            rbf[p*NRBF + kk + 1] = __expf(-GAMf*u1*u1);
        }
        __syncthreads();
        // z_p = b1 + rbf_p @ W1  (f32x2, W1 amortized over 8 pairs)
        ull Z[CPCH] = {0,0,0,0,0,0,0,0};
        #pragma unroll
        for (int k4 = 0; k4 < NRBF; k4 += 4) {
            float w0 = W1[(k4+0)*FDIM+lt], w1 = W1[(k4+1)*FDIM+lt];
            float w2 = W1[(k4+2)*FDIM+lt], w3 = W1[(k4+3)*FDIM+lt];
            ull wp0 = pk2(w0, w1), wp1 = pk2(w2, w3);
            #pragma unroll
            for (int p = 0; p < CPCH; p++) {
                ulonglong2 r = *(const ulonglong2*)&rbf[p*NRBF + k4];
                fma2(Z[p], r.x, wp0); fma2(Z[p], r.y, wp1);
            }
        }
        #pragma unroll
        for (int p = 0; p < CPCH; p++) {
            float z = b1t + hadd2(Z[p]);
            sA[p*FDIM + lt] = fmaxf(z, 0.0f);
            unsigned mk = __ballot_sync(0xffffffffu, z > 0.0f);
            if ((lt & 31) == 0 && sVal[p] > 0.0f)
                g_relu[(pbase + p)*4 + warp] = mk;
        }
        __syncthreads();
        // filt_p[lt] = b2 + sum_f A_p[f] * W2[f,lt]  (W2T rows, amortized x8)
        ull F[CPCH] = {0,0,0,0,0,0,0,0};
        #pragma unroll 8
        for (int f4 = 0; f4 < FDIM; f4 += 4) {
            ulonglong2 w = *(const ulonglong2*)&g_W2T[lt*FDIM + f4];
            #pragma unroll
            for (int p = 0; p < CPCH; p++) {
                ulonglong2 a = *(const ulonglong2*)&sA[p*FDIM + f4];
                fma2(F[p], a.x, w.x); fma2(F[p], a.y, w.y);
            }
        }
        #pragma unroll
        for (int p = 0; p < CPCH; p++) {
            if (sVal[p] > 0.0f) {
                float filt = b2t + hadd2(F[p]);
                atomicAdd(&g_m[sI[p]*FDIM + lt], filt * g_h[sJ[p]*FDIM + lt]);
            }
        }
        __syncthreads();
    }
}

// ---------------------------------------------------------------------------
// K5: per-atom head: a = m@W3 ; gm = W3 @ (w_out * 1[a>0])
__global__ void k_head(const float* __restrict__ W3, const float* __restrict__ w_out) {
    __shared__ float sM[FDIM], sB[FDIM];
    int i = blockIdx.x, lt = threadIdx.x;
    sM[lt] = g_m[i*FDIM + lt];
    __syncthreads();
    float a = 0.0f;
    #pragma unroll 8
    for (int f = 0; f < FDIM; f++) a = fmaf(sM[f], W3[f*FDIM + lt], a);
    sB[lt] = (a > 0.0f) ? w_out[lt] : 0.0f;
    __syncthreads();
    float gm = 0.0f;
    #pragma unroll 8
    for (int f = 0; f < FDIM; f++) gm = fmaf(sB[f], g_W3T[f*FDIM + lt], gm);
    g_gm[i*FDIM + lt] = gm;
}

// ---------------------------------------------------------------------------
// K6: backward, pair-parallel. relu mask from g_relu (no z recompute).
__global__ void __launch_bounds__(128)
k_bwdP(const float* __restrict__ q, const float* __restrict__ W1,
       const float* __restrict__ W2) {
    __shared__ float crbf[CPCH*NRBF];
    __shared__ float sgf [CPCH*FDIM];
    __shared__ float sRed[CPCH*4];
    __shared__ float sD  [CPCH*4];
    __shared__ int   sI[CPCH], sJ[CPCH];
    __shared__ float sVal[CPCH];
    int lt = threadIdx.x, warp = lt >> 5, lane = lt & 31;
    int np = g_np;
    int nch = (np + CPCH - 1) / CPCH;

    for (int c = blockIdx.x; c < nch; c += gridDim.x) {
        int pbase = c * CPCH;
        if (lt < CPCH) {
            int pidx = pbase + lt;
            bool v = pidx < np;
            int i = v ? g_pi[pidx] : 0;
            int j = v ? g_pj[pidx] : 0;
            sI[lt] = i; sJ[lt] = j; sVal[lt] = v ? 1.0f : 0.0f;
            float dx = q[3*i]-q[3*j], dy = q[3*i+1]-q[3*j+1], dz = q[3*i+2]-q[3*j+2];
            float d = v ? sqrtf(dx*dx + dy*dy + dz*dz) : 1.0f;
            sD[lt*4+0] = dx; sD[lt*4+1] = dy; sD[lt*4+2] = dz; sD[lt*4+3] = d;
        }
        __syncthreads();
        {   // crbf_k = -2*gamma*(d - c_k)*rbf_k
            int p = lt >> 4, kk = (lt & 15) * 2;
            float d = sD[p*4+3];
            float u0 = d - (float)kk*CSPf, u1 = d - (float)(kk+1)*CSPf;
            crbf[p*NRBF + kk]     = -2.0f*GAMf*u0*__expf(-GAMf*u0*u0);
            crbf[p*NRBF + kk + 1] = -2.0f*GAMf*u1*__expf(-GAMf*u1*u1);
        }
        #pragma unroll
        for (int p = 0; p < CPCH; p++)
            sgf[p*FDIM + lt] = g_gm[sI[p]*FDIM + lt] * g_h[sJ[p]*FDIM + lt];
        __syncthreads();
        // c_p = (W1^T @ crbf_p)_lt
        ull C[CPCH] = {0,0,0,0,0,0,0,0};
        #pragma unroll
        for (int k4 = 0; k4 < NRBF; k4 += 4) {
            float w0 = W1[(k4+0)*FDIM+lt], w1 = W1[(k4+1)*FDIM+lt];
            float w2 = W1[(k4+2)*FDIM+lt], w3 = W1[(k4+3)*FDIM+lt];
            ull wp0 = pk2(w0, w1), wp1 = pk2(w2, w3);
            #pragma unroll
            for (int p = 0; p < CPCH; p++) {
                ulonglong2 r = *(const ulonglong2*)&crbf[p*NRBF + k4];
                fma2(C[p], r.x, wp0); fma2(C[p], r.y, wp1);
            }
        }
        float cf[CPCH];
        #pragma unroll
        for (int p = 0; p < CPCH; p++) cf[p] = hadd2(C[p]);
        // gz_p[lt] = sum_f gfilt_p[f] * W2[lt,f]  (W2 rows, amortized x8)
        ull G[CPCH] = {0,0,0,0,0,0,0,0};
        #pragma unroll 8
        for (int f4 = 0; f4 < FDIM; f4 += 4) {
            ulonglong2 w = *(const ulonglong2*)&W2[lt*FDIM + f4];
            #pragma unroll
            for (int p = 0; p < CPCH; p++) {
                ulonglong2 a = *(const ulonglong2*)&sgf[p*FDIM + f4];
                fma2(G[p], a.x, w.x); fma2(G[p], a.y, w.y);
            }
        }
        // mask, per-pair dot reduce
        #pragma unroll
        for (int p = 0; p < CPCH; p++) {
            unsigned mk = g_relu[(pbase + p)*4 + warp];
            float pp = ((mk >> lane) & 1u) ? hadd2(G[p]) * cf[p] : 0.0f;
            #pragma unroll
            for (int off = 16; off > 0; off >>= 1)
                pp += __shfl_down_sync(0xffffffffu, pp, off);
            if (lane == 0) sRed[p*4 + warp] = pp;
        }
        __syncthreads();
        if (lt < CPCH && sVal[lt] > 0.0f) {
            float s = (sRed[lt*4+0]+sRed[lt*4+1]+sRed[lt*4+2]+sRed[lt*4+3]) / sD[lt*4+3];
            float gx = s*sD[lt*4+0], gy = s*sD[lt*4+1], gz = s*sD[lt*4+2];
            int i = sI[lt], j = sJ[lt];
            atomicAdd(&g_gq[3*i+0],  gx);
            atomicAdd(&g_gq[3*i+1],  gy);
            atomicAdd(&g_gq[3*i+2],  gz);
            atomicAdd(&g_gq[3*j+0], -gx);
            atomicAdd(&g_gq[3*j+1], -gy);
            atomicAdd(&g_gq[3*j+2], -gz);
        }
        __syncthreads();
    }
}

// ---------------------------------------------------------------------------
// K7: KE reduction + dvdt + v passthrough + Nose-Hoover chain RHS
__global__ void k_fin(const float* __restrict__ v, const float* __restrict__ mass,
                      const float* __restrict__ p_eta, float* __restrict__ out) {
    __shared__ float red[256];
    int t = threadIdx.x;
    float ke = 0.0f;
    for (int n = t; n < NA; n += 256) {
        float mn = mass[n];
        float v0 = v[3*n], v1 = v[3*n+1], v2 = v[3*n+2];
        ke += mn * (v0*v0 + v1*v1 + v2*v2);
    }
    red[t] = ke;
    __syncthreads();
    for (int off = 128; off > 0; off >>= 1) {
        if (t < off) red[t] += red[t + off];
        __syncthreads();
    }
    float pe0 = p_eta[0];
    for (int idx = t; idx < NA*3; idx += 256) {
        int n = idx / 3;
        float mn = mass[n], vv = v[idx];
        out[idx]        = (-g_gq[idx] - pe0 * mn * vv / Q0f) / mn;
        out[NA*3 + idx] = vv;
    }
    if (t == 0) {
        float s_ke = 0.5f * red[0];
        float pe1 = p_eta[1], pe2 = p_eta[2], pe3 = p_eta[3];
        out[2*NA*3 + 0] = 2.0f*(s_ke - TARGETf) - pe0*pe1/QCf;
        out[2*NA*3 + 1] = pe0*pe0/Q0f - KTf - pe1*pe2/QCf;
        out[2*NA*3 + 2] = pe1*pe1/QCf - KTf - pe2*pe3/QCf;
        out[2*NA*3 + 3] = pe2*pe2/QCf - KTf;
    }
}

// ---------------------------------------------------------------------------
extern "C" void kernel_launch(void* const* d_in, const int* in_sizes, int n_in,
                              void* d_out, int out_size) {
    const float* v     = (const float*)d_in[0];
    const float* q     = (const float*)d_in[1];
    const float* p_eta = (const float*)d_in[2];
    const float* mass  = (const float*)d_in[3];
    const float* embed = (const float*)d_in[4];
    const float* W1    = (const float*)d_in[5];
    const float* b1    = (const float*)d_in[6];
    const float* W2    = (const float*)d_in[7];
    const float* b2    = (const float*)d_in[8];
    const float* W3    = (const float*)d_in[9];
    const float* w_out = (const float*)d_in[10];
    const int*   zat   = (const int*)d_in[11];
    float* out = (float*)d_out;
    (void)in_sizes; (void)n_in; (void)out_size;

    k_prep <<<NA, FDIM>>>(embed, zat, W2, W3);
    k_nbr  <<<NA, 256 >>>(q);
    k_scan <<<1,  NA  >>>();
    k_scat <<<NA, 64  >>>();
    k_fwdP <<<PGRID, 128>>>(q, W1, b1, b2);
    k_head <<<NA, FDIM>>>(W3, w_out);
    k_bwdP <<<PGRID, 128>>>(q, W1, W2);
    k_fin  <<<1,  256 >>>(v, mass, p_eta, out);
}

// round 14
// speedup vs baseline: 1.3453x; 1.3453x over previous
#include <cuda_runtime.h>
#include <math.h>

#define NA   768
#define FDIM 128
#define NRBF 32
#define MAXNBR 192
#define MAXPAIRS (NA*MAXNBR)
#define CPCH 8                 /* pairs per chunk */
#define PGRID 296              /* 2 blocks per SM */
#define W2PAD 132              /* padded row stride (16B aligned, conflict-free .128) */

// Physics constants (match reference exactly)
#define CUT2f   25.0f
#define GAMf    40.96f                       /* (32/5)^2 */
#define CSPf    (5.0f/31.0f)                 /* RBF center spacing */
#define KBf     8.617330337217213e-05f
#define KTf     (300.0f*KBf)
#define Q0f     (2.0f*(float)(NA*3)*KTf*400.0f)
#define QCf     (2.0f*KTf*400.0f)
#define TARGETf (0.5f*(float)(NA*3)*KTf)

typedef unsigned long long ull;

// packed fp32x2 helpers (Blackwell FFMA2 — PTX-only)
__device__ __forceinline__ void fma2(ull& d, ull a, ull b) {
    asm("fma.rn.f32x2 %0, %1, %2, %0;" : "+l"(d) : "l"(a), "l"(b));
}
__device__ __forceinline__ ull pk2(float lo, float hi) {
    ull r; asm("mov.b64 %0, {%1, %2};" : "=l"(r) : "f"(lo), "f"(hi)); return r;
}
__device__ __forceinline__ float hadd2(ull v) {
    float lo, hi; asm("mov.b64 {%0, %1}, %2;" : "=f"(lo), "=f"(hi) : "l"(v));
    return lo + hi;
}
// group-scoped barrier: 128 threads, ids 1..2
__device__ __forceinline__ void barg(int id) {
    asm volatile("bar.sync %0, %1;" :: "r"(id), "r"(128) : "memory");
}

// Scratch (static __device__ arrays: allocation-free, graph-safe)
__device__ int      g_np;
__device__ int      g_pi[MAXPAIRS];
__device__ int      g_pj[MAXPAIRS];
__device__ float    g_h  [NA*FDIM];
__device__ float    g_W3T[FDIM*FDIM];
__device__ float    g_m  [NA*FDIM];          // messages (atomic accumulation)
__device__ float    g_gm [NA*FDIM];          // dE/dm per atom
__device__ float    g_gq [NA*3];             // dE/dq accumulator
__device__ unsigned g_relu[MAXPAIRS*4];      // relu(z) mask bits per (pair, warp)

// ---------------------------------------------------------------------------
// K0: gather h, zero g_m, transpose W3, reset pair cursor
__global__ void k_prep(const float* __restrict__ embed, const int* __restrict__ zat,
                       const float* __restrict__ W3) {
    int b = blockIdx.x, t = threadIdx.x;
    g_h[b*FDIM + t] = embed[zat[b]*FDIM + t];
    g_m[b*FDIM + t] = 0.0f;
    if (b < FDIM) g_W3T[b*FDIM + t] = W3[t*FDIM + b];
    if (b == 0 && t == 0) g_np = 0;
}

// ---------------------------------------------------------------------------
// K1: cutoff neighbor search -> flat directed pair list (block per atom i).
// One global atomicAdd per block reserves the output range. Zero forces.
__global__ void k_nbr(const float* __restrict__ q) {
    __shared__ float sq[NA*3];
    __shared__ int sjl[MAXNBR];
    __shared__ int scnt, sbase;
    int i = blockIdx.x, t = threadIdx.x;
    if (t == 0) scnt = 0;
    if (t < 3)  g_gq[i*3 + t] = 0.0f;
    for (int idx = t; idx < NA*3; idx += 256) sq[idx] = q[idx];
    __syncthreads();
    float qx = sq[3*i], qy = sq[3*i+1], qz = sq[3*i+2];
    for (int j = t; j < NA; j += 256) {
        if (j == i) continue;
        float dx = qx - sq[3*j], dy = qy - sq[3*j+1], dz = qz - sq[3*j+2];
        if (dx*dx + dy*dy + dz*dz < CUT2f) {
            int p = atomicAdd(&scnt, 1);
            if (p < MAXNBR) sjl[p] = j;
        }
    }
    __syncthreads();
    int cnt = (scnt < MAXNBR) ? scnt : MAXNBR;
    if (t == 0) sbase = atomicAdd(&g_np, cnt);
    __syncthreads();
    int base = sbase;
    for (int s = t; s < cnt; s += 256) {
        g_pi[base + s] = i;
        g_pj[base + s] = sjl[s];
    }
}

// ---------------------------------------------------------------------------
// K2: forward, pair-parallel. 256 threads = 2 independent 128-groups sharing
// one padded-smem W2T copy. W1 packed in registers. CPCH pairs per group-iter.
#define FWD_SMEM_FLOATS (FDIM*W2PAD + 2*1296)
__global__ void __launch_bounds__(256)
k_fwdP(const float* __restrict__ q,  const float* __restrict__ W1,
       const float* __restrict__ b1, const float* __restrict__ W2,
       const float* __restrict__ b2) {
    extern __shared__ float sm[];
    float* sW2T = sm;                                  // [128][W2PAD], W2 transposed
    int t = threadIdx.x, g = t >> 7, lt = t & 127, warp = lt >> 5;
    float* grp = sm + FDIM*W2PAD + g*1296;
    float* rbf = grp;                                  // 8*32
    float* sA  = grp + 256;                            // 8*128
    int*   sIJ = (int*)(grp + 1280);                   // 8 i + 8 j

    for (int idx = t; idx < FDIM*FDIM; idx += 256)
        sW2T[(idx & 127)*W2PAD + (idx >> 7)] = W2[idx];

    // W1 column lt packed into registers (reused for every chunk)
    ull w1p[16];
    #pragma unroll
    for (int k = 0; k < 16; k++)
        w1p[k] = pk2(W1[(2*k)*FDIM + lt], W1[(2*k+1)*FDIM + lt]);

    float b1t = b1[lt], b2t = b2[lt];
    int np = g_np;
    int nch = (np + CPCH - 1) / CPCH;
    __syncthreads();

    for (int c = blockIdx.x*2 + g; c < nch; c += gridDim.x*2) {
        int pbase = c * CPCH;
        barg(g+1);                         // prior iteration fully consumed
        if (lt < CPCH) {
            int pidx = pbase + lt;
            bool v = pidx < np;
            sIJ[lt]     = v ? g_pi[pidx] : -1;
            sIJ[8 + lt] = v ? g_pj[pidx] : 0;
        }
        barg(g+1);
        {   // rbf: 16 threads per pair, 2 k's each
            int p = lt >> 4, kk = (lt & 15) * 2;
            int i = sIJ[p]; bool v = i >= 0; if (!v) i = 0;
            int j = sIJ[8 + p];
            float dx = q[3*i]-q[3*j], dy = q[3*i+1]-q[3*j+1], dz = q[3*i+2]-q[3*j+2];
            float d = v ? sqrtf(dx*dx + dy*dy + dz*dz) : 1.0f;
            float u0 = d - (float)kk*CSPf, u1 = d - (float)(kk+1)*CSPf;
            rbf[p*NRBF + kk]     = __expf(-GAMf*u0*u0);
            rbf[p*NRBF + kk + 1] = __expf(-GAMf*u1*u1);
        }
        barg(g+1);
        // z_p = b1 + rbf_p @ W1  (W1 in regs, rbf broadcast LDS)
        ull Z[CPCH] = {0,0,0,0,0,0,0,0};
        #pragma unroll
        for (int k4 = 0; k4 < 8; k4++) {
            #pragma unroll
            for (int p = 0; p < CPCH; p++) {
                ulonglong2 r = *(const ulonglong2*)&rbf[p*NRBF + 4*k4];
                fma2(Z[p], r.x, w1p[2*k4]); fma2(Z[p], r.y, w1p[2*k4+1]);
            }
        }
        #pragma unroll
        for (int p = 0; p < CPCH; p++) {
            float z = b1t + hadd2(Z[p]);
            sA[p*FDIM + lt] = fmaxf(z, 0.0f);
            unsigned mk = __ballot_sync(0xffffffffu, z > 0.0f);
            if ((lt & 31) == 0 && sIJ[p] >= 0)
                g_relu[(pbase + p)*4 + warp] = mk;
        }
        barg(g+1);
        // filt_p[lt] = b2 + sum_f A_p[f] * W2[f,lt]  (padded W2T rows)
        ull F[CPCH] = {0,0,0,0,0,0,0,0};
        #pragma unroll 8
        for (int f4 = 0; f4 < FDIM; f4 += 4) {
            ulonglong2 w = *(const ulonglong2*)&sW2T[lt*W2PAD + f4];
            #pragma unroll
            for (int p = 0; p < CPCH; p++) {
                ulonglong2 a = *(const ulonglong2*)&sA[p*FDIM + f4];
                fma2(F[p], a.x, w.x); fma2(F[p], a.y, w.y);
            }
        }
        #pragma unroll
        for (int p = 0; p < CPCH; p++) {
            int i = sIJ[p];
            if (i >= 0) {
                float filt = b2t + hadd2(F[p]);
                atomicAdd(&g_m[i*FDIM + lt], filt * g_h[sIJ[8+p]*FDIM + lt]);
            }
        }
    }
}

// ---------------------------------------------------------------------------
// K3: per-atom head: a = m@W3 ; gm = W3 @ (w_out * 1[a>0])
__global__ void k_head(const float* __restrict__ W3, const float* __restrict__ w_out) {
    __shared__ float sM[FDIM], sB[FDIM];
    int i = blockIdx.x, lt = threadIdx.x;
    sM[lt] = g_m[i*FDIM + lt];
    __syncthreads();
    float a = 0.0f;
    #pragma unroll 8
    for (int f = 0; f < FDIM; f++) a = fmaf(sM[f], W3[f*FDIM + lt], a);
    sB[lt] = (a > 0.0f) ? w_out[lt] : 0.0f;
    __syncthreads();
    float gm = 0.0f;
    #pragma unroll 8
    for (int f = 0; f < FDIM; f++) gm = fmaf(sB[f], g_W3T[f*FDIM + lt], gm);
    g_gm[i*FDIM + lt] = gm;
}

// ---------------------------------------------------------------------------
// K4: backward, pair-parallel. Same 2-group structure; W2 rows from padded
// smem (row-major as-is); relu masks from g_relu (no z recompute).
#define BWD_SMEM_FLOATS (FDIM*W2PAD + 2*1360)
__global__ void __launch_bounds__(256)
k_bwdP(const float* __restrict__ q, const float* __restrict__ W1,
       const float* __restrict__ W2) {
    extern __shared__ float sm[];
    float* sW2 = sm;                                   // [128][W2PAD], row-major
    int t = threadIdx.x, g = t >> 7, lt = t & 127, warp = lt >> 5, lane = t & 31;
    float* grp  = sm + FDIM*W2PAD + g*1360;
    float* crbf = grp;                                 // 8*32
    float* sgf  = grp + 256;                           // 8*128
    float* sRed = grp + 1280;                          // 32
    float* sD   = grp + 1312;                          // 32: {dx,dy,dz,d} x 8
    int*   sIJ  = (int*)(grp + 1344);                  // 8 i + 8 j

    for (int idx = t; idx < FDIM*FDIM; idx += 256)
        sW2[(idx >> 7)*W2PAD + (idx & 127)] = W2[idx];

    ull w1p[16];
    #pragma unroll
    for (int k = 0; k < 16; k++)
        w1p[k] = pk2(W1[(2*k)*FDIM + lt], W1[(2*k+1)*FDIM + lt]);

    int np = g_np;
    int nch = (np + CPCH - 1) / CPCH;
    __syncthreads();

    for (int c = blockIdx.x*2 + g; c < nch; c += gridDim.x*2) {
        int pbase = c * CPCH;
        barg(g+1);
        if (lt < CPCH) {
            int pidx = pbase + lt;
            bool v = pidx < np;
            sIJ[lt]     = v ? g_pi[pidx] : -1;
            sIJ[8 + lt] = v ? g_pj[pidx] : 0;
        }
        barg(g+1);
        {   // crbf + geometry
            int p = lt >> 4, kk = (lt & 15) * 2;
            int i = sIJ[p]; bool v = i >= 0; if (!v) i = 0;
            int j = sIJ[8 + p];
            float dx = q[3*i]-q[3*j], dy = q[3*i+1]-q[3*j+1], dz = q[3*i+2]-q[3*j+2];
            float d = v ? sqrtf(dx*dx + dy*dy + dz*dz) : 1.0f;
            float u0 = d - (float)kk*CSPf, u1 = d - (float)(kk+1)*CSPf;
            crbf[p*NRBF + kk]     = -2.0f*GAMf*u0*__expf(-GAMf*u0*u0);
            crbf[p*NRBF + kk + 1] = -2.0f*GAMf*u1*__expf(-GAMf*u1*u1);
            if (kk == 0) { sD[p*4+0]=dx; sD[p*4+1]=dy; sD[p*4+2]=dz; sD[p*4+3]=d; }
        }
        #pragma unroll
        for (int p = 0; p < CPCH; p++) {
            int i = sIJ[p];
            sgf[p*FDIM + lt] = (i >= 0) ? g_gm[i*FDIM + lt] * g_h[sIJ[8+p]*FDIM + lt]
                                        : 0.0f;
        }
        barg(g+1);
        // c_p = (W1^T @ crbf_p)_lt  (W1 in regs)
        ull C[CPCH] = {0,0,0,0,0,0,0,0};
        #pragma unroll
        for (int k4 = 0; k4 < 8; k4++) {
            #pragma unroll
            for (int p = 0; p < CPCH; p++) {
                ulonglong2 r = *(const ulonglong2*)&crbf[p*NRBF + 4*k4];
                fma2(C[p], r.x, w1p[2*k4]); fma2(C[p], r.y, w1p[2*k4+1]);
            }
        }
        float cf[CPCH];
        #pragma unroll
        for (int p = 0; p < CPCH; p++) cf[p] = hadd2(C[p]);
        // gz_p[lt] = sum_f gfilt_p[f] * W2[lt,f]  (padded W2 rows)
        ull G[CPCH] = {0,0,0,0,0,0,0,0};
        #pragma unroll 8
        for (int f4 = 0; f4 < FDIM; f4 += 4) {
            ulonglong2 w = *(const ulonglong2*)&sW2[lt*W2PAD + f4];
            #pragma unroll
            for (int p = 0; p < CPCH; p++) {
                ulonglong2 a = *(const ulonglong2*)&sgf[p*FDIM + f4];
                fma2(G[p], a.x, w.x); fma2(G[p], a.y, w.y);
            }
        }
        // mask + per-pair dot reduce
        #pragma unroll
        for (int p = 0; p < CPCH; p++) {
            unsigned mk = (sIJ[p] >= 0) ? g_relu[(pbase + p)*4 + warp] : 0u;
            float pp = ((mk >> lane) & 1u) ? hadd2(G[p]) * cf[p] : 0.0f;
            #pragma unroll
            for (int off = 16; off > 0; off >>= 1)
                pp += __shfl_down_sync(0xffffffffu, pp, off);
            if (lane == 0) sRed[p*4 + warp] = pp;
        }
        barg(g+1);
        if (lt < CPCH && sIJ[lt] >= 0) {
            float s = (sRed[lt*4+0]+sRed[lt*4+1]+sRed[lt*4+2]+sRed[lt*4+3]) / sD[lt*4+3];
            float gx = s*sD[lt*4+0], gy = s*sD[lt*4+1], gz = s*sD[lt*4+2];
            int i = sIJ[lt], j = sIJ[8 + lt];
            atomicAdd(&g_gq[3*i+0],  gx);
            atomicAdd(&g_gq[3*i+1],  gy);
            atomicAdd(&g_gq[3*i+2],  gz);
            atomicAdd(&g_gq[3*j+0], -gx);
            atomicAdd(&g_gq[3*j+1], -gy);
            atomicAdd(&g_gq[3*j+2], -gz);
        }
    }
}

// ---------------------------------------------------------------------------
// K5: KE reduction + dvdt + v passthrough + Nose-Hoover chain RHS
__global__ void k_fin(const float* __restrict__ v, const float* __restrict__ mass,
                      const float* __restrict__ p_eta, float* __restrict__ out) {
    __shared__ float red[256];
    int t = threadIdx.x;
    float ke = 0.0f;
    for (int n = t; n < NA; n += 256) {
        float mn = mass[n];
        float v0 = v[3*n], v1 = v[3*n+1], v2 = v[3*n+2];
        ke += mn * (v0*v0 + v1*v1 + v2*v2);
    }
    red[t] = ke;
    __syncthreads();
    for (int off = 128; off > 0; off >>= 1) {
        if (t < off) red[t] += red[t + off];
        __syncthreads();
    }
    float pe0 = p_eta[0];
    for (int idx = t; idx < NA*3; idx += 256) {
        int n = idx / 3;
        float mn = mass[n], vv = v[idx];
        out[idx]        = (-g_gq[idx] - pe0 * mn * vv / Q0f) / mn;
        out[NA*3 + idx] = vv;
    }
    if (t == 0) {
        float s_ke = 0.5f * red[0];
        float pe1 = p_eta[1], pe2 = p_eta[2], pe3 = p_eta[3];
        out[2*NA*3 + 0] = 2.0f*(s_ke - TARGETf) - pe0*pe1/QCf;
        out[2*NA*3 + 1] = pe0*pe0/Q0f - KTf - pe1*pe2/QCf;
        out[2*NA*3 + 2] = pe1*pe1/QCf - KTf - pe2*pe3/QCf;
        out[2*NA*3 + 3] = pe2*pe2/QCf - KTf;
    }
}

// ---------------------------------------------------------------------------
extern "C" void kernel_launch(void* const* d_in, const int* in_sizes, int n_in,
                              void* d_out, int out_size) {
    const float* v     = (const float*)d_in[0];
    const float* q     = (const float*)d_in[1];
    const float* p_eta = (const float*)d_in[2];
    const float* mass  = (const float*)d_in[3];
    const float* embed = (const float*)d_in[4];
    const float* W1    = (const float*)d_in[5];
    const float* b1    = (const float*)d_in[6];
    const float* W2    = (const float*)d_in[7];
    const float* b2    = (const float*)d_in[8];
    const float* W3    = (const float*)d_in[9];
    const float* w_out = (const float*)d_in[10];
    const int*   zat   = (const int*)d_in[11];
    float* out = (float*)d_out;
    (void)in_sizes; (void)n_in; (void)out_size;

    const int fwd_smem = FWD_SMEM_FLOATS * (int)sizeof(float);   // ~76 KB
    const int bwd_smem = BWD_SMEM_FLOATS * (int)sizeof(float);   // ~77 KB
    cudaFuncSetAttribute(k_fwdP, cudaFuncAttributeMaxDynamicSharedMemorySize, fwd_smem);
    cudaFuncSetAttribute(k_bwdP, cudaFuncAttributeMaxDynamicSharedMemorySize, bwd_smem);

    k_prep <<<NA, FDIM>>>(embed, zat, W3);
    k_nbr  <<<NA, 256 >>>(q);
    k_fwdP <<<PGRID, 256, fwd_smem>>>(q, W1, b1, W2, b2);
    k_head <<<NA, FDIM>>>(W3, w_out);
    k_bwdP <<<PGRID, 256, bwd_smem>>>(q, W1, W2);
    k_fin  <<<1,  256 >>>(v, mass, p_eta, out);
}

// round 15
// speedup vs baseline: 1.3777x; 1.0241x over previous
#include <cuda_runtime.h>
#include <math.h>

#define NA   768
#define FDIM 128
#define NRBF 32
#define MAXNBR 192
#define MAXPAIRS (NA*MAXNBR)
#define CPCH 8                 /* pairs per chunk */
#define PGRID 296              /* 2 blocks per SM */
#define W2PAD 132              /* padded row stride (16B aligned, conflict-free .128) */

// Physics constants (match reference exactly)
#define CUT2f   25.0f
#define GAMf    40.96f                       /* (32/5)^2 */
#define CSPf    (5.0f/31.0f)                 /* RBF center spacing */
#define KBf     8.617330337217213e-05f
#define KTf     (300.0f*KBf)
#define Q0f     (2.0f*(float)(NA*3)*KTf*400.0f)
#define QCf     (2.0f*KTf*400.0f)
#define TARGETf (0.5f*(float)(NA*3)*KTf)

typedef unsigned long long ull;

// packed fp32x2 helpers (Blackwell FFMA2 — PTX-only)
__device__ __forceinline__ void fma2(ull& d, ull a, ull b) {
    asm("fma.rn.f32x2 %0, %1, %2, %0;" : "+l"(d) : "l"(a), "l"(b));
}
__device__ __forceinline__ ull pk2(float lo, float hi) {
    ull r; asm("mov.b64 %0, {%1, %2};" : "=l"(r) : "f"(lo), "f"(hi)); return r;
}
__device__ __forceinline__ float hadd2(ull v) {
    float lo, hi; asm("mov.b64 {%0, %1}, %2;" : "=f"(lo), "=f"(hi) : "l"(v));
    return lo + hi;
}
// group-scoped barrier: 128 threads, ids 1..2
__device__ __forceinline__ void barg(int id) {
    asm volatile("bar.sync %0, %1;" :: "r"(id), "r"(128) : "memory");
}

// Scratch (static __device__ arrays: allocation-free, graph-safe)
__device__ int      g_np;
__device__ int      g_pi[MAXPAIRS];
__device__ int      g_pj[MAXPAIRS];
__device__ float    g_h  [NA*FDIM];
__device__ float    g_W3T[FDIM*FDIM];
__device__ float    g_m  [NA*FDIM];          // messages (atomic accumulation)
__device__ float    g_gm [NA*FDIM];          // dE/dm per atom
__device__ float    g_gq [NA*3];             // dE/dq accumulator
__device__ unsigned g_relu[MAXPAIRS*4];      // relu(z) mask bits per (pair, warp)

// ---------------------------------------------------------------------------
// K0: gather h, zero g_m, transpose W3, reset pair cursor
__global__ void k_prep(const float* __restrict__ embed, const int* __restrict__ zat,
                       const float* __restrict__ W3) {
    int b = blockIdx.x, t = threadIdx.x;
    g_h[b*FDIM + t] = embed[zat[b]*FDIM + t];
    g_m[b*FDIM + t] = 0.0f;
    if (b < FDIM) g_W3T[b*FDIM + t] = W3[t*FDIM + b];
    if (b == 0 && t == 0) g_np = 0;
}

// ---------------------------------------------------------------------------
// K1: cutoff neighbor search -> flat directed pair list (block per atom i).
__global__ void k_nbr(const float* __restrict__ q) {
    __shared__ float sq[NA*3];
    __shared__ int sjl[MAXNBR];
    __shared__ int scnt, sbase;
    int i = blockIdx.x, t = threadIdx.x;
    if (t == 0) scnt = 0;
    if (t < 3)  g_gq[i*3 + t] = 0.0f;
    for (int idx = t; idx < NA*3; idx += 256) sq[idx] = q[idx];
    __syncthreads();
    float qx = sq[3*i], qy = sq[3*i+1], qz = sq[3*i+2];
    for (int j = t; j < NA; j += 256) {
        if (j == i) continue;
        float dx = qx - sq[3*j], dy = qy - sq[3*j+1], dz = qz - sq[3*j+2];
        if (dx*dx + dy*dy + dz*dz < CUT2f) {
            int p = atomicAdd(&scnt, 1);
            if (p < MAXNBR) sjl[p] = j;
        }
    }
    __syncthreads();
    int cnt = (scnt < MAXNBR) ? scnt : MAXNBR;
    if (t == 0) sbase = atomicAdd(&g_np, cnt);
    __syncthreads();
    int base = sbase;
    for (int s = t; s < cnt; s += 256) {
        g_pi[base + s] = i;
        g_pj[base + s] = sjl[s];
    }
}

// ---------------------------------------------------------------------------
// K2: forward, pair-parallel. 256 threads = 2 independent 128-groups sharing
// one padded-smem W2T copy. W1 packed in registers. CPCH pairs per group-iter.
#define FWD_SMEM_FLOATS (FDIM*W2PAD + 2*1296)
__global__ void __launch_bounds__(256)
k_fwdP(const float* __restrict__ q,  const float* __restrict__ W1,
       const float* __restrict__ b1, const float* __restrict__ W2,
       const float* __restrict__ b2) {
    extern __shared__ float sm[];
    float* sW2T = sm;                                  // [128][W2PAD], W2 transposed
    int t = threadIdx.x, g = t >> 7, lt = t & 127, warp = lt >> 5;
    float* grp = sm + FDIM*W2PAD + g*1296;
    float* rbf = grp;                                  // 8*32
    float* sA  = grp + 256;                            // 8*128
    int*   sIJ = (int*)(grp + 1280);                   // 8 i + 8 j

    for (int idx = t; idx < FDIM*FDIM; idx += 256)
        sW2T[(idx & 127)*W2PAD + (idx >> 7)] = W2[idx];

    // W1 column lt packed into registers (reused for every chunk)
    ull w1p[16];
    #pragma unroll
    for (int k = 0; k < 16; k++)
        w1p[k] = pk2(W1[(2*k)*FDIM + lt], W1[(2*k+1)*FDIM + lt]);

    float b1t = b1[lt], b2t = b2[lt];
    int np = g_np;
    int nch = (np + CPCH - 1) / CPCH;
    __syncthreads();

    for (int c = blockIdx.x*2 + g; c < nch; c += gridDim.x*2) {
        int pbase = c * CPCH;
        barg(g+1);                         // prior iteration fully consumed
        if (lt < CPCH) {
            int pidx = pbase + lt;
            bool v = pidx < np;
            sIJ[lt]     = v ? g_pi[pidx] : -1;
            sIJ[8 + lt] = v ? g_pj[pidx] : 0;
        }
        barg(g+1);
        {   // rbf: 16 threads per pair, 2 k's each
            int p = lt >> 4, kk = (lt & 15) * 2;
            int i = sIJ[p]; bool v = i >= 0; if (!v) i = 0;
            int j = sIJ[8 + p];
            float dx = q[3*i]-q[3*j], dy = q[3*i+1]-q[3*j+1], dz = q[3*i+2]-q[3*j+2];
            float d = v ? sqrtf(dx*dx + dy*dy + dz*dz) : 1.0f;
            float u0 = d - (float)kk*CSPf, u1 = d - (float)(kk+1)*CSPf;
            rbf[p*NRBF + kk]     = __expf(-GAMf*u0*u0);
            rbf[p*NRBF + kk + 1] = __expf(-GAMf*u1*u1);
        }
        barg(g+1);
        // z_p = b1 + rbf_p @ W1  (W1 in regs, rbf broadcast LDS)
        ull Z[CPCH] = {0,0,0,0,0,0,0,0};
        #pragma unroll
        for (int k4 = 0; k4 < 8; k4++) {
            #pragma unroll
            for (int p = 0; p < CPCH; p++) {
                ulonglong2 r = *(const ulonglong2*)&rbf[p*NRBF + 4*k4];
                fma2(Z[p], r.x, w1p[2*k4]); fma2(Z[p], r.y, w1p[2*k4+1]);
            }
        }
        #pragma unroll
        for (int p = 0; p < CPCH; p++) {
            float z = b1t + hadd2(Z[p]);
            sA[p*FDIM + lt] = fmaxf(z, 0.0f);
            unsigned mk = __ballot_sync(0xffffffffu, z > 0.0f);
            if ((lt & 31) == 0 && sIJ[p] >= 0)
                g_relu[(pbase + p)*4 + warp] = mk;
        }
        barg(g+1);
        // filt_p[lt] = b2 + sum_f A_p[f] * W2[f,lt]  (padded W2T rows)
        ull F[CPCH] = {0,0,0,0,0,0,0,0};
        #pragma unroll 8
        for (int f4 = 0; f4 < FDIM; f4 += 4) {
            ulonglong2 w = *(const ulonglong2*)&sW2T[lt*W2PAD + f4];
            #pragma unroll
            for (int p = 0; p < CPCH; p++) {
                ulonglong2 a = *(const ulonglong2*)&sA[p*FDIM + f4];
                fma2(F[p], a.x, w.x); fma2(F[p], a.y, w.y);
            }
        }
        #pragma unroll
        for (int p = 0; p < CPCH; p++) {
            int i = sIJ[p];
            if (i >= 0) {
                float filt = b2t + hadd2(F[p]);
                atomicAdd(&g_m[i*FDIM + lt], filt * g_h[sIJ[8+p]*FDIM + lt]);
            }
        }
    }
}

// ---------------------------------------------------------------------------
// K3: per-atom head: a = m@W3 ; gm = W3 @ (w_out * 1[a>0]).
// 256 threads = 2 atoms per block; 4-way ILP accumulators (chain 128 -> 32).
__global__ void __launch_bounds__(256)
k_head(const float* __restrict__ W3, const float* __restrict__ w_out) {
    __shared__ float sM[2*FDIM], sB[2*FDIM];
    int t = threadIdx.x, g = t >> 7, lt = t & 127;
    int i = blockIdx.x*2 + g;
    float* mM = sM + g*FDIM;
    float* mB = sB + g*FDIM;
    mM[lt] = g_m[i*FDIM + lt];
    barg(g+1);
    float a0 = 0.f, a1 = 0.f, a2 = 0.f, a3 = 0.f;
    #pragma unroll 8
    for (int f = 0; f < FDIM; f += 4) {
        a0 = fmaf(mM[f+0], W3[(f+0)*FDIM + lt], a0);
        a1 = fmaf(mM[f+1], W3[(f+1)*FDIM + lt], a1);
        a2 = fmaf(mM[f+2], W3[(f+2)*FDIM + lt], a2);
        a3 = fmaf(mM[f+3], W3[(f+3)*FDIM + lt], a3);
    }
    float a = (a0 + a1) + (a2 + a3);
    mB[lt] = (a > 0.0f) ? w_out[lt] : 0.0f;
    barg(g+1);
    float g0 = 0.f, g1 = 0.f, g2 = 0.f, g3 = 0.f;
    #pragma unroll 8
    for (int f = 0; f < FDIM; f += 4) {
        g0 = fmaf(mB[f+0], g_W3T[(f+0)*FDIM + lt], g0);
        g1 = fmaf(mB[f+1], g_W3T[(f+1)*FDIM + lt], g1);
        g2 = fmaf(mB[f+2], g_W3T[(f+2)*FDIM + lt], g2);
        g3 = fmaf(mB[f+3], g_W3T[(f+3)*FDIM + lt], g3);
    }
    g_gm[i*FDIM + lt] = (g0 + g1) + (g2 + g3);
}

// ---------------------------------------------------------------------------
// K4: backward, pair-parallel. Same 2-group structure; W2 rows from padded
// smem (row-major as-is); relu masks from g_relu (no z recompute).
#define BWD_SMEM_FLOATS (FDIM*W2PAD + 2*1360)
__global__ void __launch_bounds__(256)
k_bwdP(const float* __restrict__ q, const float* __restrict__ W1,
       const float* __restrict__ W2) {
    extern __shared__ float sm[];
    float* sW2 = sm;                                   // [128][W2PAD], row-major
    int t = threadIdx.x, g = t >> 7, lt = t & 127, warp = lt >> 5, lane = t & 31;
    float* grp  = sm + FDIM*W2PAD + g*1360;
    float* crbf = grp;                                 // 8*32
    float* sgf  = grp + 256;                           // 8*128
    float* sRed = grp + 1280;                          // 32
    float* sD   = grp + 1312;                          // 32: {dx,dy,dz,d} x 8
    int*   sIJ  = (int*)(grp + 1344);                  // 8 i + 8 j

    for (int idx = t; idx < FDIM*FDIM; idx += 256)
        sW2[(idx >> 7)*W2PAD + (idx & 127)] = W2[idx];

    ull w1p[16];
    #pragma unroll
    for (int k = 0; k < 16; k++)
        w1p[k] = pk2(W1[(2*k)*FDIM + lt], W1[(2*k+1)*FDIM + lt]);

    int np = g_np;
    int nch = (np + CPCH - 1) / CPCH;
    __syncthreads();

    for (int c = blockIdx.x*2 + g; c < nch; c += gridDim.x*2) {
        int pbase = c * CPCH;
        barg(g+1);
        if (lt < CPCH) {
            int pidx = pbase + lt;
            bool v = pidx < np;
            sIJ[lt]     = v ? g_pi[pidx] : -1;
            sIJ[8 + lt] = v ? g_pj[pidx] : 0;
        }
        barg(g+1);
        {   // crbf + geometry
            int p = lt >> 4, kk = (lt & 15) * 2;
            int i = sIJ[p]; bool v = i >= 0; if (!v) i = 0;
            int j = sIJ[8 + p];
            float dx = q[3*i]-q[3*j], dy = q[3*i+1]-q[3*j+1], dz = q[3*i+2]-q[3*j+2];
            float d = v ? sqrtf(dx*dx + dy*dy + dz*dz) : 1.0f;
            float u0 = d - (float)kk*CSPf, u1 = d - (float)(kk+1)*CSPf;
            crbf[p*NRBF + kk]     = -2.0f*GAMf*u0*__expf(-GAMf*u0*u0);
            crbf[p*NRBF + kk + 1] = -2.0f*GAMf*u1*__expf(-GAMf*u1*u1);
            if (kk == 0) { sD[p*4+0]=dx; sD[p*4+1]=dy; sD[p*4+2]=dz; sD[p*4+3]=d; }
        }
        #pragma unroll
        for (int p = 0; p < CPCH; p++) {
            int i = sIJ[p];
            sgf[p*FDIM + lt] = (i >= 0) ? g_gm[i*FDIM + lt] * g_h[sIJ[8+p]*FDIM + lt]
                                        : 0.0f;
        }
        barg(g+1);
        // c_p = (W1^T @ crbf_p)_lt  (W1 in regs)
        ull C[CPCH] = {0,0,0,0,0,0,0,0};
        #pragma unroll
        for (int k4 = 0; k4 < 8; k4++) {
            #pragma unroll
            for (int p = 0; p < CPCH; p++) {
                ulonglong2 r = *(const ulonglong2*)&crbf[p*NRBF + 4*k4];
                fma2(C[p], r.x, w1p[2*k4]); fma2(C[p], r.y, w1p[2*k4+1]);
            }
        }
        float cf[CPCH];
        #pragma unroll
        for (int p = 0; p < CPCH; p++) cf[p] = hadd2(C[p]);
        // gz_p[lt] = sum_f gfilt_p[f] * W2[lt,f]  (padded W2 rows)
        ull G[CPCH] = {0,0,0,0,0,0,0,0};
        #pragma unroll 8
        for (int f4 = 0; f4 < FDIM; f4 += 4) {
            ulonglong2 w = *(const ulonglong2*)&sW2[lt*W2PAD + f4];
            #pragma unroll
            for (int p = 0; p < CPCH; p++) {
                ulonglong2 a = *(const ulonglong2*)&sgf[p*FDIM + f4];
                fma2(G[p], a.x, w.x); fma2(G[p], a.y, w.y);
            }
        }
        // mask + per-pair dot reduce
        #pragma unroll
        for (int p = 0; p < CPCH; p++) {
            unsigned mk = (sIJ[p] >= 0) ? g_relu[(pbase + p)*4 + warp] : 0u;
            float pp = ((mk >> lane) & 1u) ? hadd2(G[p]) * cf[p] : 0.0f;
            #pragma unroll
            for (int off = 16; off > 0; off >>= 1)
                pp += __shfl_down_sync(0xffffffffu, pp, off);
            if (lane == 0) sRed[p*4 + warp] = pp;
        }
        barg(g+1);
        if (lt < CPCH && sIJ[lt] >= 0) {
            float s = (sRed[lt*4+0]+sRed[lt*4+1]+sRed[lt*4+2]+sRed[lt*4+3]) / sD[lt*4+3];
            float gx = s*sD[lt*4+0], gy = s*sD[lt*4+1], gz = s*sD[lt*4+2];
            int i = sIJ[lt], j = sIJ[8 + lt];
            atomicAdd(&g_gq[3*i+0],  gx);
            atomicAdd(&g_gq[3*i+1],  gy);
            atomicAdd(&g_gq[3*i+2],  gz);
            atomicAdd(&g_gq[3*j+0], -gx);
            atomicAdd(&g_gq[3*j+1], -gy);
            atomicAdd(&g_gq[3*j+2], -gz);
        }
    }
}

// ---------------------------------------------------------------------------
// K5: KE reduction + dvdt + v passthrough + Nose-Hoover chain RHS
__global__ void k_fin(const float* __restrict__ v, const float* __restrict__ mass,
                      const float* __restrict__ p_eta, float* __restrict__ out) {
    __shared__ float red[256];
    int t = threadIdx.x;
    float k0 = 0.f, k1 = 0.f, k2 = 0.f;
    for (int n = t; n < NA; n += 256) {
        float mn = mass[n];
        float v0 = v[3*n], v1 = v[3*n+1], v2 = v[3*n+2];
        k0 = fmaf(mn*v0, v0, k0);
        k1 = fmaf(mn*v1, v1, k1);
        k2 = fmaf(mn*v2, v2, k2);
    }
    red[t] = (k0 + k1) + k2;
    __syncthreads();
    for (int off = 128; off > 0; off >>= 1) {
        if (t < off) red[t] += red[t + off];
        __syncthreads();
    }
    float pe0 = p_eta[0];
    for (int idx = t; idx < NA*3; idx += 256) {
        int n = idx / 3;
        float mn = mass[n], vv = v[idx];
        out[idx]        = (-g_gq[idx] - pe0 * mn * vv / Q0f) / mn;
        out[NA*3 + idx] = vv;
    }
    if (t == 0) {
        float s_ke = 0.5f * red[0];
        float pe1 = p_eta[1], pe2 = p_eta[2], pe3 = p_eta[3];
        out[2*NA*3 + 0] = 2.0f*(s_ke - TARGETf) - pe0*pe1/QCf;
        out[2*NA*3 + 1] = pe0*pe0/Q0f - KTf - pe1*pe2/QCf;
        out[2*NA*3 + 2] = pe1*pe1/QCf - KTf - pe2*pe3/QCf;
        out[2*NA*3 + 3] = pe2*pe2/QCf - KTf;
    }
}

// ---------------------------------------------------------------------------
extern "C" void kernel_launch(void* const* d_in, const int* in_sizes, int n_in,
                              void* d_out, int out_size) {
    const float* v     = (const float*)d_in[0];
    const float* q     = (const float*)d_in[1];
    const float* p_eta = (const float*)d_in[2];
    const float* mass  = (const float*)d_in[3];
    const float* embed = (const float*)d_in[4];
    const float* W1    = (const float*)d_in[5];
    const float* b1    = (const float*)d_in[6];
    const float* W2    = (const float*)d_in[7];
    const float* b2    = (const float*)d_in[8];
    const float* W3    = (const float*)d_in[9];
    const float* w_out = (const float*)d_in[10];
    const int*   zat   = (const int*)d_in[11];
    float* out = (float*)d_out;
    (void)in_sizes; (void)n_in; (void)out_size;

    const int fwd_smem = FWD_SMEM_FLOATS * (int)sizeof(float);   // ~76 KB
    const int bwd_smem = BWD_SMEM_FLOATS * (int)sizeof(float);   // ~77 KB
    cudaFuncSetAttribute(k_fwdP, cudaFuncAttributeMaxDynamicSharedMemorySize, fwd_smem);
    cudaFuncSetAttribute(k_bwdP, cudaFuncAttributeMaxDynamicSharedMemorySize, bwd_smem);

    k_prep <<<NA, FDIM>>>(embed, zat, W3);
    k_nbr  <<<NA, 256 >>>(q);
    k_fwdP <<<PGRID, 256, fwd_smem>>>(q, W1, b1, W2, b2);
    k_head <<<NA/2, 256>>>(W3, w_out);
    k_bwdP <<<PGRID, 256, bwd_smem>>>(q, W1, W2);
    k_fin  <<<1,  256 >>>(v, mass, p_eta, out);
}

// round 16
// speedup vs baseline: 1.5250x; 1.1069x over previous
#include <cuda_runtime.h>
#include <math.h>

#define NA   768
#define FDIM 128
#define NRBF 32
#define MAXNBR 192
#define MAXPAIRS (NA*MAXNBR/2)
#define CPCH 8                 /* pairs per chunk */
#define PGRID 296              /* 2 blocks per SM */
#define W2PAD 132              /* padded row stride (16B aligned, conflict-free .128) */

// Physics constants (match reference exactly)
#define CUT2f   25.0f
#define GAMf    40.96f                       /* (32/5)^2 */
#define CSPf    (5.0f/31.0f)                 /* RBF center spacing */
#define KBf     8.617330337217213e-05f
#define KTf     (300.0f*KBf)
#define Q0f     (2.0f*(float)(NA*3)*KTf*400.0f)
#define QCf     (2.0f*KTf*400.0f)
#define TARGETf (0.5f*(float)(NA*3)*KTf)

typedef unsigned long long ull;

// packed fp32x2 helpers (Blackwell FFMA2 — PTX-only)
__device__ __forceinline__ void fma2(ull& d, ull a, ull b) {
    asm("fma.rn.f32x2 %0, %1, %2, %0;" : "+l"(d) : "l"(a), "l"(b));
}
__device__ __forceinline__ ull pk2(float lo, float hi) {
    ull r; asm("mov.b64 %0, {%1, %2};" : "=l"(r) : "f"(lo), "f"(hi)); return r;
}
__device__ __forceinline__ float hadd2(ull v) {
    float lo, hi; asm("mov.b64 {%0, %1}, %2;" : "=f"(lo), "=f"(hi) : "l"(v));
    return lo + hi;
}
// group-scoped barrier: 128 threads, ids 1..2
__device__ __forceinline__ void barg(int id) {
    asm volatile("bar.sync %0, %1;" :: "r"(id), "r"(128) : "memory");
}

// Scratch (static __device__ arrays: allocation-free, graph-safe)
__device__ int      g_np;
__device__ int      g_pi[MAXPAIRS];
__device__ int      g_pj[MAXPAIRS];
__device__ float    g_h  [NA*FDIM];
__device__ float    g_W3T[FDIM*FDIM];
__device__ float    g_m  [NA*FDIM];          // messages (atomic accumulation)
__device__ float    g_gm [NA*FDIM];          // dE/dm per atom
__device__ float    g_gq [NA*3];             // dE/dq accumulator
__device__ unsigned g_relu[MAXPAIRS*4];      // relu(z) mask bits per (undirected pair, warp)

// ---------------------------------------------------------------------------
// K0: gather h, zero g_m, transpose W3, reset pair cursor
__global__ void k_prep(const float* __restrict__ embed, const int* __restrict__ zat,
                       const float* __restrict__ W3) {
    int b = blockIdx.x, t = threadIdx.x;
    g_h[b*FDIM + t] = embed[zat[b]*FDIM + t];
    g_m[b*FDIM + t] = 0.0f;
    if (b < FDIM) g_W3T[b*FDIM + t] = W3[t*FDIM + b];
    if (b == 0 && t == 0) g_np = 0;
}

// ---------------------------------------------------------------------------
// K1: cutoff neighbor search -> flat UNDIRECTED pair list (block per atom i,
// scans only j > i). One global atomicAdd per block reserves the range.
__global__ void k_nbr(const float* __restrict__ q) {
    __shared__ float sq[NA*3];
    __shared__ int sjl[MAXNBR];
    __shared__ int scnt, sbase;
    int i = blockIdx.x, t = threadIdx.x;
    if (t == 0) scnt = 0;
    if (t < 3)  g_gq[i*3 + t] = 0.0f;
    for (int idx = t; idx < NA*3; idx += 256) sq[idx] = q[idx];
    __syncthreads();
    float qx = sq[3*i], qy = sq[3*i+1], qz = sq[3*i+2];
    for (int j = i + 1 + t; j < NA; j += 256) {
        float dx = qx - sq[3*j], dy = qy - sq[3*j+1], dz = qz - sq[3*j+2];
        if (dx*dx + dy*dy + dz*dz < CUT2f) {
            int p = atomicAdd(&scnt, 1);
            if (p < MAXNBR) sjl[p] = j;
        }
    }
    __syncthreads();
    int cnt = (scnt < MAXNBR) ? scnt : MAXNBR;
    if (t == 0) sbase = atomicAdd(&g_np, cnt);
    __syncthreads();
    int base = sbase;
    for (int s = t; s < cnt; s += 256) {
        g_pi[base + s] = i;
        g_pj[base + s] = sjl[s];
    }
}

// ---------------------------------------------------------------------------
// K2: forward, undirected-pair-parallel. 256 threads = 2 independent
// 128-groups sharing one padded-smem W2T copy; W1 packed in registers.
// Each pair scatters to BOTH endpoint messages (filt is symmetric).
#define FWD_SMEM_FLOATS (FDIM*W2PAD + 2*1296)
__global__ void __launch_bounds__(256)
k_fwdP(const float* __restrict__ q,  const float* __restrict__ W1,
       const float* __restrict__ b1, const float* __restrict__ W2,
       const float* __restrict__ b2) {
    extern __shared__ float sm[];
    float* sW2T = sm;                                  // [128][W2PAD], W2 transposed
    int t = threadIdx.x, g = t >> 7, lt = t & 127, warp = lt >> 5;
    float* grp = sm + FDIM*W2PAD + g*1296;
    float* rbf = grp;                                  // 8*32
    float* sA  = grp + 256;                            // 8*128
    int*   sIJ = (int*)(grp + 1280);                   // 8 i + 8 j

    for (int idx = t; idx < FDIM*FDIM; idx += 256)
        sW2T[(idx & 127)*W2PAD + (idx >> 7)] = W2[idx];

    // W1 column lt packed into registers (reused for every chunk)
    ull w1p[16];
    #pragma unroll
    for (int k = 0; k < 16; k++)
        w1p[k] = pk2(W1[(2*k)*FDIM + lt], W1[(2*k+1)*FDIM + lt]);

    float b1t = b1[lt], b2t = b2[lt];
    int np = g_np;
    int nch = (np + CPCH - 1) / CPCH;
    __syncthreads();

    for (int c = blockIdx.x*2 + g; c < nch; c += gridDim.x*2) {
        int pbase = c * CPCH;
        barg(g+1);                         // prior iteration fully consumed
        if (lt < CPCH) {
            int pidx = pbase + lt;
            bool v = pidx < np;
            sIJ[lt]     = v ? g_pi[pidx] : -1;
            sIJ[8 + lt] = v ? g_pj[pidx] : 0;
        }
        barg(g+1);
        {   // rbf: 16 threads per pair, 2 k's each
            int p = lt >> 4, kk = (lt & 15) * 2;
            int i = sIJ[p]; bool v = i >= 0; if (!v) i = 0;
            int j = sIJ[8 + p];
            float dx = q[3*i]-q[3*j], dy = q[3*i+1]-q[3*j+1], dz = q[3*i+2]-q[3*j+2];
            float d = v ? sqrtf(dx*dx + dy*dy + dz*dz) : 1.0f;
            float u0 = d - (float)kk*CSPf, u1 = d - (float)(kk+1)*CSPf;
            rbf[p*NRBF + kk]     = __expf(-GAMf*u0*u0);
            rbf[p*NRBF + kk + 1] = __expf(-GAMf*u1*u1);
        }
        barg(g+1);
        // z_p = b1 + rbf_p @ W1  (W1 in regs, rbf broadcast LDS)
        ull Z[CPCH] = {0,0,0,0,0,0,0,0};
        #pragma unroll
        for (int k4 = 0; k4 < 8; k4++) {
            #pragma unroll
            for (int p = 0; p < CPCH; p++) {
                ulonglong2 r = *(const ulonglong2*)&rbf[p*NRBF + 4*k4];
                fma2(Z[p], r.x, w1p[2*k4]); fma2(Z[p], r.y, w1p[2*k4+1]);
            }
        }
        #pragma unroll
        for (int p = 0; p < CPCH; p++) {
            float z = b1t + hadd2(Z[p]);
            sA[p*FDIM + lt] = fmaxf(z, 0.0f);
            unsigned mk = __ballot_sync(0xffffffffu, z > 0.0f);
            if ((lt & 31) == 0 && sIJ[p] >= 0)
                g_relu[(pbase + p)*4 + warp] = mk;
        }
        barg(g+1);
        // filt_p[lt] = b2 + sum_f A_p[f] * W2[f,lt]  (padded W2T rows)
        ull F[CPCH] = {0,0,0,0,0,0,0,0};
        #pragma unroll 8
        for (int f4 = 0; f4 < FDIM; f4 += 4) {
            ulonglong2 w = *(const ulonglong2*)&sW2T[lt*W2PAD + f4];
            #pragma unroll
            for (int p = 0; p < CPCH; p++) {
                ulonglong2 a = *(const ulonglong2*)&sA[p*FDIM + f4];
                fma2(F[p], a.x, w.x); fma2(F[p], a.y, w.y);
            }
        }
        #pragma unroll
        for (int p = 0; p < CPCH; p++) {
            int i = sIJ[p];
            if (i >= 0) {
                int j = sIJ[8 + p];
                float filt = b2t + hadd2(F[p]);
                atomicAdd(&g_m[i*FDIM + lt], filt * g_h[j*FDIM + lt]);
                atomicAdd(&g_m[j*FDIM + lt], filt * g_h[i*FDIM + lt]);
            }
        }
    }
}

// ---------------------------------------------------------------------------
// K3: per-atom head: a = m@W3 ; gm = W3 @ (w_out * 1[a>0]).
// Thread lt reads CONTIGUOUS rows: W3T[lt,:] for a, W3[lt,:] for gm
// (vector LDG.128 + f32x2). 2 atoms per 256-thread block.
__global__ void __launch_bounds__(256)
k_head(const float* __restrict__ W3, const float* __restrict__ w_out) {
    __shared__ __align__(16) float sM[2*FDIM], sB[2*FDIM];
    int t = threadIdx.x, g = t >> 7, lt = t & 127;
    int i = blockIdx.x*2 + g;
    float* mM = sM + g*FDIM;
    float* mB = sB + g*FDIM;
    mM[lt] = g_m[i*FDIM + lt];
    barg(g+1);
    // a = sum_f m[f] * W3[f,lt] = sum_f m[f] * W3T[lt,f]  (contiguous)
    ull A0 = 0, A1 = 0;
    const ulonglong2* wa = (const ulonglong2*)(g_W3T + lt*FDIM);
    const ulonglong2* mv = (const ulonglong2*)mM;
    #pragma unroll
    for (int k = 0; k < 32; k += 2) {
        ulonglong2 w0 = wa[k], w1 = wa[k+1];
        ulonglong2 m0 = mv[k], m1 = mv[k+1];
        fma2(A0, m0.x, w0.x); fma2(A0, m0.y, w0.y);
        fma2(A1, m1.x, w1.x); fma2(A1, m1.y, w1.y);
    }
    float a = hadd2(A0) + hadd2(A1);
    mB[lt] = (a > 0.0f) ? w_out[lt] : 0.0f;
    barg(g+1);
    // gm[lt] = sum_f b[f] * W3[lt,f]  (contiguous row of W3)
    ull G0 = 0, G1 = 0;
    const ulonglong2* wg = (const ulonglong2*)(W3 + lt*FDIM);
    const ulonglong2* bv = (const ulonglong2*)mB;
    #pragma unroll
    for (int k = 0; k < 32; k += 2) {
        ulonglong2 w0 = wg[k], w1 = wg[k+1];
        ulonglong2 b0 = bv[k], b1 = bv[k+1];
        fma2(G0, b0.x, w0.x); fma2(G0, b0.y, w0.y);
        fma2(G1, b1.x, w1.x); fma2(G1, b1.y, w1.y);
    }
    g_gm[i*FDIM + lt] = hadd2(G0) + hadd2(G1);
}

// ---------------------------------------------------------------------------
// K4: backward, undirected-pair-parallel. Combined gradient:
//   gz_ij + gz_ji = mask ⊙ W2^T(gm_i⊙h_j + gm_j⊙h_i)  — ONE matmul per pair.
#define BWD_SMEM_FLOATS (FDIM*W2PAD + 2*1360)
__global__ void __launch_bounds__(256)
k_bwdP(const float* __restrict__ q, const float* __restrict__ W1,
       const float* __restrict__ W2) {
    extern __shared__ float sm[];
    float* sW2 = sm;                                   // [128][W2PAD], row-major
    int t = threadIdx.x, g = t >> 7, lt = t & 127, warp = lt >> 5, lane = t & 31;
    float* grp  = sm + FDIM*W2PAD + g*1360;
    float* crbf = grp;                                 // 8*32
    float* sgf  = grp + 256;                           // 8*128
    float* sRed = grp + 1280;                          // 32
    float* sD   = grp + 1312;                          // 32: {dx,dy,dz,d} x 8
    int*   sIJ  = (int*)(grp + 1344);                  // 8 i + 8 j

    for (int idx = t; idx < FDIM*FDIM; idx += 256)
        sW2[(idx >> 7)*W2PAD + (idx & 127)] = W2[idx];

    ull w1p[16];
    #pragma unroll
    for (int k = 0; k < 16; k++)
        w1p[k] = pk2(W1[(2*k)*FDIM + lt], W1[(2*k+1)*FDIM + lt]);

    int np = g_np;
    int nch = (np + CPCH - 1) / CPCH;
    __syncthreads();

    for (int c = blockIdx.x*2 + g; c < nch; c += gridDim.x*2) {
        int pbase = c * CPCH;
        barg(g+1);
        if (lt < CPCH) {
            int pidx = pbase + lt;
            bool v = pidx < np;
            sIJ[lt]     = v ? g_pi[pidx] : -1;
            sIJ[8 + lt] = v ? g_pj[pidx] : 0;
        }
        barg(g+1);
        {   // crbf + geometry
            int p = lt >> 4, kk = (lt & 15) * 2;
            int i = sIJ[p]; bool v = i >= 0; if (!v) i = 0;
            int j = sIJ[8 + p];
            float dx = q[3*i]-q[3*j], dy = q[3*i+1]-q[3*j+1], dz = q[3*i+2]-q[3*j+2];
            float d = v ? sqrtf(dx*dx + dy*dy + dz*dz) : 1.0f;
            float u0 = d - (float)kk*CSPf, u1 = d - (float)(kk+1)*CSPf;
            crbf[p*NRBF + kk]     = -2.0f*GAMf*u0*__expf(-GAMf*u0*u0);
            crbf[p*NRBF + kk + 1] = -2.0f*GAMf*u1*__expf(-GAMf*u1*u1);
            if (kk == 0) { sD[p*4+0]=dx; sD[p*4+1]=dy; sD[p*4+2]=dz; sD[p*4+3]=d; }
        }
        #pragma unroll
        for (int p = 0; p < CPCH; p++) {
            int i = sIJ[p];
            if (i >= 0) {
                int j = sIJ[8 + p];
                sgf[p*FDIM + lt] = g_gm[i*FDIM + lt] * g_h[j*FDIM + lt]
                                 + g_gm[j*FDIM + lt] * g_h[i*FDIM + lt];
            } else {
                sgf[p*FDIM + lt] = 0.0f;
            }
        }
        barg(g+1);
        // c_p = (W1^T @ crbf_p)_lt  (W1 in regs)
        ull C[CPCH] = {0,0,0,0,0,0,0,0};
        #pragma unroll
        for (int k4 = 0; k4 < 8; k4++) {
            #pragma unroll
            for (int p = 0; p < CPCH; p++) {
                ulonglong2 r = *(const ulonglong2*)&crbf[p*NRBF + 4*k4];
                fma2(C[p], r.x, w1p[2*k4]); fma2(C[p], r.y, w1p[2*k4+1]);
            }
        }
        float cf[CPCH];
        #pragma unroll
        for (int p = 0; p < CPCH; p++) cf[p] = hadd2(C[p]);
        // gz_p[lt] = sum_f gfilt_p[f] * W2[lt,f]  (padded W2 rows)
        ull G[CPCH] = {0,0,0,0,0,0,0,0};
        #pragma unroll 8
        for (int f4 = 0; f4 < FDIM; f4 += 4) {
            ulonglong2 w = *(const ulonglong2*)&sW2[lt*W2PAD + f4];
            #pragma unroll
            for (int p = 0; p < CPCH; p++) {
                ulonglong2 a = *(const ulonglong2*)&sgf[p*FDIM + f4];
                fma2(G[p], a.x, w.x); fma2(G[p], a.y, w.y);
            }
        }
        // mask + per-pair dot reduce
        #pragma unroll
        for (int p = 0; p < CPCH; p++) {
            unsigned mk = (sIJ[p] >= 0) ? g_relu[(pbase + p)*4 + warp] : 0u;
            float pp = ((mk >> lane) & 1u) ? hadd2(G[p]) * cf[p] : 0.0f;
            #pragma unroll
            for (int off = 16; off > 0; off >>= 1)
                pp += __shfl_down_sync(0xffffffffu, pp, off);
            if (lane == 0) sRed[p*4 + warp] = pp;
        }
        barg(g+1);
        if (lt < CPCH && sIJ[lt] >= 0) {
            float s = (sRed[lt*4+0]+sRed[lt*4+1]+sRed[lt*4+2]+sRed[lt*4+3]) / sD[lt*4+3];
            float gx = s*sD[lt*4+0], gy = s*sD[lt*4+1], gz = s*sD[lt*4+2];
            int i = sIJ[lt], j = sIJ[8 + lt];
            atomicAdd(&g_gq[3*i+0],  gx);
            atomicAdd(&g_gq[3*i+1],  gy);
            atomicAdd(&g_gq[3*i+2],  gz);
            atomicAdd(&g_gq[3*j+0], -gx);
            atomicAdd(&g_gq[3*j+1], -gy);
            atomicAdd(&g_gq[3*j+2], -gz);
        }
    }
}

// ---------------------------------------------------------------------------
// K5: KE reduction + dvdt + v passthrough + Nose-Hoover chain RHS
__global__ void k_fin(const float* __restrict__ v, const float* __restrict__ mass,
                      const float* __restrict__ p_eta, float* __restrict__ out) {
    __shared__ float red[256];
    int t = threadIdx.x;
    float k0 = 0.f, k1 = 0.f, k2 = 0.f;
    for (int n = t; n < NA; n += 256) {
        float mn = mass[n];
        float v0 = v[3*n], v1 = v[3*n+1], v2 = v[3*n+2];
        k0 = fmaf(mn*v0, v0, k0);
        k1 = fmaf(mn*v1, v1, k1);
        k2 = fmaf(mn*v2, v2, k2);
    }
    red[t] = (k0 + k1) + k2;
    __syncthreads();
    for (int off = 128; off > 0; off >>= 1) {
        if (t < off) red[t] += red[t + off];
        __syncthreads();
    }
    float pe0 = p_eta[0];
    for (int idx = t; idx < NA*3; idx += 256) {
        int n = idx / 3;
        float mn = mass[n], vv = v[idx];
        out[idx]        = (-g_gq[idx] - pe0 * mn * vv / Q0f) / mn;
        out[NA*3 + idx] = vv;
    }
    if (t == 0) {
        float s_ke = 0.5f * red[0];
        float pe1 = p_eta[1], pe2 = p_eta[2], pe3 = p_eta[3];
        out[2*NA*3 + 0] = 2.0f*(s_ke - TARGETf) - pe0*pe1/QCf;
        out[2*NA*3 + 1] = pe0*pe0/Q0f - KTf - pe1*pe2/QCf;
        out[2*NA*3 + 2] = pe1*pe1/QCf - KTf - pe2*pe3/QCf;
        out[2*NA*3 + 3] = pe2*pe2/QCf - KTf;
    }
}

// ---------------------------------------------------------------------------
extern "C" void kernel_launch(void* const* d_in, const int* in_sizes, int n_in,
                              void* d_out, int out_size) {
    const float* v     = (const float*)d_in[0];
    const float* q     = (const float*)d_in[1];
    const float* p_eta = (const float*)d_in[2];
    const float* mass  = (const float*)d_in[3];
    const float* embed = (const float*)d_in[4];
    const float* W1    = (const float*)d_in[5];
    const float* b1    = (const float*)d_in[6];
    const float* W2    = (const float*)d_in[7];
    const float* b2    = (const float*)d_in[8];
    const float* W3    = (const float*)d_in[9];
    const float* w_out = (const float*)d_in[10];
    const int*   zat   = (const int*)d_in[11];
    float* out = (float*)d_out;
    (void)in_sizes; (void)n_in; (void)out_size;

    const int fwd_smem = FWD_SMEM_FLOATS * (int)sizeof(float);   // ~76 KB
    const int bwd_smem = BWD_SMEM_FLOATS * (int)sizeof(float);   // ~77 KB
    cudaFuncSetAttribute(k_fwdP, cudaFuncAttributeMaxDynamicSharedMemorySize, fwd_smem);
    cudaFuncSetAttribute(k_bwdP, cudaFuncAttributeMaxDynamicSharedMemorySize, bwd_smem);

    k_prep <<<NA, FDIM>>>(embed, zat, W3);
    k_nbr  <<<NA, 256 >>>(q);
    k_fwdP <<<PGRID, 256, fwd_smem>>>(q, W1, b1, W2, b2);
    k_head <<<NA/2, 256>>>(W3, w_out);
    k_bwdP <<<PGRID, 256, bwd_smem>>>(q, W1, W2);
    k_fin  <<<1,  256 >>>(v, mass, p_eta, out);
}

// round 17
// speedup vs baseline: 1.8254x; 1.1970x over previous
#include <cuda_runtime.h>
#include <math.h>

#define NA   768
#define FDIM 128
#define NRBF 32
#define MAXNBR 192
#define MAXPAIRS (NA*MAXNBR/2)
#define CPCH 8                 /* pairs per chunk */
#define PGRID 296              /* 2 blocks per SM */
#define W2PAD 132              /* padded row stride (16B aligned, conflict-free .128) */

// Physics constants (match reference exactly)
#define CUT2f   25.0f
#define GAMf    40.96f                       /* (32/5)^2 */
#define CSPf    (5.0f/31.0f)                 /* RBF center spacing */
#define KBf     8.617330337217213e-05f
#define KTf     (300.0f*KBf)
#define Q0f     (2.0f*(float)(NA*3)*KTf*400.0f)
#define QCf     (2.0f*KTf*400.0f)
#define TARGETf (0.5f*(float)(NA*3)*KTf)

typedef unsigned long long ull;

// packed fp32x2 helpers (Blackwell FFMA2 — PTX-only)
__device__ __forceinline__ void fma2(ull& d, ull a, ull b) {
    asm("fma.rn.f32x2 %0, %1, %2, %0;" : "+l"(d) : "l"(a), "l"(b));
}
__device__ __forceinline__ ull pk2(float lo, float hi) {
    ull r; asm("mov.b64 %0, {%1, %2};" : "=l"(r) : "f"(lo), "f"(hi)); return r;
}
__device__ __forceinline__ float hadd2(ull v) {
    float lo, hi; asm("mov.b64 {%0, %1}, %2;" : "=f"(lo), "=f"(hi) : "l"(v));
    return lo + hi;
}
// group-scoped barrier: 128 threads, ids 1..2
__device__ __forceinline__ void barg(int id) {
    asm volatile("bar.sync %0, %1;" :: "r"(id), "r"(128) : "memory");
}

// Scratch (static __device__ arrays: allocation-free, graph-safe)
__device__ int      g_np;
__device__ int      g_pi[MAXPAIRS];
__device__ int      g_pj[MAXPAIRS];
__device__ float    g_h  [NA*FDIM];
__device__ float    g_m  [NA*FDIM];          // messages (atomic accumulation)
__device__ float    g_gm [NA*FDIM];          // dE/dm per atom
__device__ float    g_gq [NA*3];             // dE/dq accumulator
__device__ unsigned g_relu[MAXPAIRS*4];      // relu(z) mask bits per (undirected pair, warp)

// ---------------------------------------------------------------------------
// K0: gather h, zero g_m, reset pair cursor
__global__ void k_prep(const float* __restrict__ embed, const int* __restrict__ zat) {
    int b = blockIdx.x, t = threadIdx.x;
    g_h[b*FDIM + t] = embed[zat[b]*FDIM + t];
    g_m[b*FDIM + t] = 0.0f;
    if (b == 0 && t == 0) g_np = 0;
}

// ---------------------------------------------------------------------------
// K1: cutoff neighbor search -> flat UNDIRECTED pair list (block per atom i,
// scans only j > i). One global atomicAdd per block reserves the range.
__global__ void k_nbr(const float* __restrict__ q) {
    __shared__ float sq[NA*3];
    __shared__ int sjl[MAXNBR];
    __shared__ int scnt, sbase;
    int i = blockIdx.x, t = threadIdx.x;
    if (t == 0) scnt = 0;
    if (t < 3)  g_gq[i*3 + t] = 0.0f;
    for (int idx = t; idx < NA*3; idx += 256) sq[idx] = q[idx];
    __syncthreads();
    float qx = sq[3*i], qy = sq[3*i+1], qz = sq[3*i+2];
    for (int j = i + 1 + t; j < NA; j += 256) {
        float dx = qx - sq[3*j], dy = qy - sq[3*j+1], dz = qz - sq[3*j+2];
        if (dx*dx + dy*dy + dz*dz < CUT2f) {
            int p = atomicAdd(&scnt, 1);
            if (p < MAXNBR) sjl[p] = j;
        }
    }
    __syncthreads();
    int cnt = (scnt < MAXNBR) ? scnt : MAXNBR;
    if (t == 0) sbase = atomicAdd(&g_np, cnt);
    __syncthreads();
    int base = sbase;
    for (int s = t; s < cnt; s += 256) {
        g_pi[base + s] = i;
        g_pj[base + s] = sjl[s];
    }
}

// ---------------------------------------------------------------------------
// K2: forward, undirected-pair-parallel. 256 threads = 2 independent
// 128-groups sharing one padded-smem W2T copy; W1 packed in registers.
// Each pair scatters to BOTH endpoint messages (filt is symmetric).
#define FWD_SMEM_FLOATS (FDIM*W2PAD + 2*1296)
__global__ void __launch_bounds__(256)
k_fwdP(const float* __restrict__ q,  const float* __restrict__ W1,
       const float* __restrict__ b1, const float* __restrict__ W2,
       const float* __restrict__ b2) {
    extern __shared__ float sm[];
    float* sW2T = sm;                                  // [128][W2PAD], W2 transposed
    int t = threadIdx.x, g = t >> 7, lt = t & 127, warp = lt >> 5;
    float* grp = sm + FDIM*W2PAD + g*1296;
    float* rbf = grp;                                  // 8*32
    float* sA  = grp + 256;                            // 8*128
    int*   sIJ = (int*)(grp + 1280);                   // 8 i + 8 j

    for (int idx = t; idx < FDIM*FDIM; idx += 256)
        sW2T[(idx & 127)*W2PAD + (idx >> 7)] = W2[idx];

    // W1 column lt packed into registers (reused for every chunk)
    ull w1p[16];
    #pragma unroll
    for (int k = 0; k < 16; k++)
        w1p[k] = pk2(W1[(2*k)*FDIM + lt], W1[(2*k+1)*FDIM + lt]);

    float b1t = b1[lt], b2t = b2[lt];
    int np = g_np;
    int nch = (np + CPCH - 1) / CPCH;
    __syncthreads();

    for (int c = blockIdx.x*2 + g; c < nch; c += gridDim.x*2) {
        int pbase = c * CPCH;
        barg(g+1);                         // prior iteration fully consumed
        if (lt < CPCH) {
            int pidx = pbase + lt;
            bool v = pidx < np;
            sIJ[lt]     = v ? g_pi[pidx] : -1;
            sIJ[8 + lt] = v ? g_pj[pidx] : 0;
        }
        barg(g+1);
        {   // rbf: 16 threads per pair, 2 k's each
            int p = lt >> 4, kk = (lt & 15) * 2;
            int i = sIJ[p]; bool v = i >= 0; if (!v) i = 0;
            int j = sIJ[8 + p];
            float dx = q[3*i]-q[3*j], dy = q[3*i+1]-q[3*j+1], dz = q[3*i+2]-q[3*j+2];
            float d = v ? sqrtf(dx*dx + dy*dy + dz*dz) : 1.0f;
            float u0 = d - (float)kk*CSPf, u1 = d - (float)(kk+1)*CSPf;
            rbf[p*NRBF + kk]     = __expf(-GAMf*u0*u0);
            rbf[p*NRBF + kk + 1] = __expf(-GAMf*u1*u1);
        }
        barg(g+1);
        // z_p = b1 + rbf_p @ W1  (W1 in regs, rbf broadcast LDS)
        ull Z[CPCH] = {0,0,0,0,0,0,0,0};
        #pragma unroll
        for (int k4 = 0; k4 < 8; k4++) {
            #pragma unroll
            for (int p = 0; p < CPCH; p++) {
                ulonglong2 r = *(const ulonglong2*)&rbf[p*NRBF + 4*k4];
                fma2(Z[p], r.x, w1p[2*k4]); fma2(Z[p], r.y, w1p[2*k4+1]);
            }
        }
        #pragma unroll
        for (int p = 0; p < CPCH; p++) {
            float z = b1t + hadd2(Z[p]);
            sA[p*FDIM + lt] = fmaxf(z, 0.0f);
            unsigned mk = __ballot_sync(0xffffffffu, z > 0.0f);
            if ((lt & 31) == 0 && sIJ[p] >= 0)
                g_relu[(pbase + p)*4 + warp] = mk;
        }
        barg(g+1);
        // filt_p[lt] = b2 + sum_f A_p[f] * W2[f,lt]  (padded W2T rows)
        ull F[CPCH] = {0,0,0,0,0,0,0,0};
        #pragma unroll 8
        for (int f4 = 0; f4 < FDIM; f4 += 4) {
            ulonglong2 w = *(const ulonglong2*)&sW2T[lt*W2PAD + f4];
            #pragma unroll
            for (int p = 0; p < CPCH; p++) {
                ulonglong2 a = *(const ulonglong2*)&sA[p*FDIM + f4];
                fma2(F[p], a.x, w.x); fma2(F[p], a.y, w.y);
            }
        }
        #pragma unroll
        for (int p = 0; p < CPCH; p++) {
            int i = sIJ[p];
            if (i >= 0) {
                int j = sIJ[8 + p];
                float filt = b2t + hadd2(F[p]);
                atomicAdd(&g_m[i*FDIM + lt], filt * g_h[j*FDIM + lt]);
                atomicAdd(&g_m[j*FDIM + lt], filt * g_h[i*FDIM + lt]);
            }
        }
    }
}

// ---------------------------------------------------------------------------
// K3: per-atom head: a = m@W3 ; gm = W3 @ (w_out * 1[a>0]).
// Persistent blocks: W3T AND W3 cached once per block in PADDED smem
// (conflict-free LDS.128 row reads); grid-stride over atom pairs.
#define HEAD_SMEM_FLOATS (2*FDIM*W2PAD + 4*FDIM)
__global__ void __launch_bounds__(256)
k_head(const float* __restrict__ W3, const float* __restrict__ w_out) {
    extern __shared__ float sm[];
    float* sW3T = sm;                                  // [128][W2PAD]: W3T[c][r]=W3[r][c]
    float* sW3  = sm + FDIM*W2PAD;                     // [128][W2PAD]: W3 row-major
    int t = threadIdx.x, g = t >> 7, lt = t & 127;
    float* mM = sm + 2*FDIM*W2PAD + g*2*FDIM;          // per-group m buffer
    float* mB = mM + FDIM;                             // per-group masked w_out

    for (int idx = t; idx < FDIM*FDIM; idx += 256) {
        int r = idx >> 7, cc = idx & 127;
        float w = W3[idx];
        sW3T[cc*W2PAD + r] = w;
        sW3 [r*W2PAD + cc] = w;
    }
    float wot = w_out[lt];
    __syncthreads();

    for (int c = blockIdx.x; c < NA/2; c += gridDim.x) {
        int i = c*2 + g;
        barg(g+1);                       // prior chunk fully consumed
        mM[lt] = g_m[i*FDIM + lt];
        barg(g+1);
        // a[lt] = sum_f m[f] * W3[f,lt] = row lt of sW3T (padded, conflict-free)
        ull A0 = 0, A1 = 0;
        #pragma unroll 8
        for (int f = 0; f < FDIM; f += 8) {
            ulonglong2 w0 = *(const ulonglong2*)&sW3T[lt*W2PAD + f];
            ulonglong2 w1 = *(const ulonglong2*)&sW3T[lt*W2PAD + f + 4];
            ulonglong2 m0 = *(const ulonglong2*)&mM[f];
            ulonglong2 m1 = *(const ulonglong2*)&mM[f + 4];
            fma2(A0, m0.x, w0.x); fma2(A0, m0.y, w0.y);
            fma2(A1, m1.x, w1.x); fma2(A1, m1.y, w1.y);
        }
        float a = hadd2(A0) + hadd2(A1);
        mB[lt] = (a > 0.0f) ? wot : 0.0f;
        barg(g+1);
        // gm[lt] = sum_f b[f] * W3[lt,f] = row lt of sW3 (padded, conflict-free)
        ull G0 = 0, G1 = 0;
        #pragma unroll 8
        for (int f = 0; f < FDIM; f += 8) {
            ulonglong2 w0 = *(const ulonglong2*)&sW3[lt*W2PAD + f];
            ulonglong2 w1 = *(const ulonglong2*)&sW3[lt*W2PAD + f + 4];
            ulonglong2 b0 = *(const ulonglong2*)&mB[f];
            ulonglong2 b1 = *(const ulonglong2*)&mB[f + 4];
            fma2(G0, b0.x, w0.x); fma2(G0, b0.y, w0.y);
            fma2(G1, b1.x, w1.x); fma2(G1, b1.y, w1.y);
        }
        g_gm[i*FDIM + lt] = hadd2(G0) + hadd2(G1);
    }
}

// ---------------------------------------------------------------------------
// K4: backward, undirected-pair-parallel. Combined gradient:
//   gz_ij + gz_ji = mask ⊙ W2^T(gm_i⊙h_j + gm_j⊙h_i)  — ONE matmul per pair.
#define BWD_SMEM_FLOATS (FDIM*W2PAD + 2*1360)
__global__ void __launch_bounds__(256)
k_bwdP(const float* __restrict__ q, const float* __restrict__ W1,
       const float* __restrict__ W2) {
    extern __shared__ float sm[];
    float* sW2 = sm;                                   // [128][W2PAD], row-major
    int t = threadIdx.x, g = t >> 7, lt = t & 127, warp = lt >> 5, lane = t & 31;
    float* grp  = sm + FDIM*W2PAD + g*1360;
    float* crbf = grp;                                 // 8*32
    float* sgf  = grp + 256;                           // 8*128
    float* sRed = grp + 1280;                          // 32
    float* sD   = grp + 1312;                          // 32: {dx,dy,dz,d} x 8
    int*   sIJ  = (int*)(grp + 1344);                  // 8 i + 8 j

    for (int idx = t; idx < FDIM*FDIM; idx += 256)
        sW2[(idx >> 7)*W2PAD + (idx & 127)] = W2[idx];

    ull w1p[16];
    #pragma unroll
    for (int k = 0; k < 16; k++)
        w1p[k] = pk2(W1[(2*k)*FDIM + lt], W1[(2*k+1)*FDIM + lt]);

    int np = g_np;
    int nch = (np + CPCH - 1) / CPCH;
    __syncthreads();

    for (int c = blockIdx.x*2 + g; c < nch; c += gridDim.x*2) {
        int pbase = c * CPCH;
        barg(g+1);
        if (lt < CPCH) {
            int pidx = pbase + lt;
            bool v = pidx < np;
            sIJ[lt]     = v ? g_pi[pidx] : -1;
            sIJ[8 + lt] = v ? g_pj[pidx] : 0;
        }
        barg(g+1);
        {   // crbf + geometry
            int p = lt >> 4, kk = (lt & 15) * 2;
            int i = sIJ[p]; bool v = i >= 0; if (!v) i = 0;
            int j = sIJ[8 + p];
            float dx = q[3*i]-q[3*j], dy = q[3*i+1]-q[3*j+1], dz = q[3*i+2]-q[3*j+2];
            float d = v ? sqrtf(dx*dx + dy*dy + dz*dz) : 1.0f;
            float u0 = d - (float)kk*CSPf, u1 = d - (float)(kk+1)*CSPf;
            crbf[p*NRBF + kk]     = -2.0f*GAMf*u0*__expf(-GAMf*u0*u0);
            crbf[p*NRBF + kk + 1] = -2.0f*GAMf*u1*__expf(-GAMf*u1*u1);
            if (kk == 0) { sD[p*4+0]=dx; sD[p*4+1]=dy; sD[p*4+2]=dz; sD[p*4+3]=d; }
        }
        #pragma unroll
        for (int p = 0; p < CPCH; p++) {
            int i = sIJ[p];
            if (i >= 0) {
                int j = sIJ[8 + p];
                sgf[p*FDIM + lt] = g_gm[i*FDIM + lt] * g_h[j*FDIM + lt]
                                 + g_gm[j*FDIM + lt] * g_h[i*FDIM + lt];
            } else {
                sgf[p*FDIM + lt] = 0.0f;
            }
        }
        barg(g+1);
        // c_p = (W1^T @ crbf_p)_lt  (W1 in regs)
        ull C[CPCH] = {0,0,0,0,0,0,0,0};
        #pragma unroll
        for (int k4 = 0; k4 < 8; k4++) {
            #pragma unroll
            for (int p = 0; p < CPCH; p++) {
                ulonglong2 r = *(const ulonglong2*)&crbf[p*NRBF + 4*k4];
                fma2(C[p], r.x, w1p[2*k4]); fma2(C[p], r.y, w1p[2*k4+1]);
            }
        }
        float cf[CPCH];
        #pragma unroll
        for (int p = 0; p < CPCH; p++) cf[p] = hadd2(C[p]);
        // gz_p[lt] = sum_f gfilt_p[f] * W2[lt,f]  (padded W2 rows)
        ull G[CPCH] = {0,0,0,0,0,0,0,0};
        #pragma unroll 8
        for (int f4 = 0; f4 < FDIM; f4 += 4) {
            ulonglong2 w = *(const ulonglong2*)&sW2[lt*W2PAD + f4];
            #pragma unroll
            for (int p = 0; p < CPCH; p++) {
                ulonglong2 a = *(const ulonglong2*)&sgf[p*FDIM + f4];
                fma2(G[p], a.x, w.x); fma2(G[p], a.y, w.y);
            }
        }
        // mask + per-pair dot reduce
        #pragma unroll
        for (int p = 0; p < CPCH; p++) {
            unsigned mk = (sIJ[p] >= 0) ? g_relu[(pbase + p)*4 + warp] : 0u;
            float pp = ((mk >> lane) & 1u) ? hadd2(G[p]) * cf[p] : 0.0f;
            #pragma unroll
            for (int off = 16; off > 0; off >>= 1)
                pp += __shfl_down_sync(0xffffffffu, pp, off);
            if (lane == 0) sRed[p*4 + warp] = pp;
        }
        barg(g+1);
        if (lt < CPCH && sIJ[lt] >= 0) {
            float s = (sRed[lt*4+0]+sRed[lt*4+1]+sRed[lt*4+2]+sRed[lt*4+3]) / sD[lt*4+3];
            float gx = s*sD[lt*4+0], gy = s*sD[lt*4+1], gz = s*sD[lt*4+2];
            int i = sIJ[lt], j = sIJ[8 + lt];
            atomicAdd(&g_gq[3*i+0],  gx);
            atomicAdd(&g_gq[3*i+1],  gy);
            atomicAdd(&g_gq[3*i+2],  gz);
            atomicAdd(&g_gq[3*j+0], -gx);
            atomicAdd(&g_gq[3*j+1], -gy);
            atomicAdd(&g_gq[3*j+2], -gz);
        }
    }
}

// ---------------------------------------------------------------------------
// K5: KE reduction + dvdt + v passthrough + Nose-Hoover chain RHS
__global__ void k_fin(const float* __restrict__ v, const float* __restrict__ mass,
                      const float* __restrict__ p_eta, float* __restrict__ out) {
    __shared__ float red[256];
    int t = threadIdx.x;
    float k0 = 0.f, k1 = 0.f, k2 = 0.f;
    for (int n = t; n < NA; n += 256) {
        float mn = mass[n];
        float v0 = v[3*n], v1 = v[3*n+1], v2 = v[3*n+2];
        k0 = fmaf(mn*v0, v0, k0);
        k1 = fmaf(mn*v1, v1, k1);
        k2 = fmaf(mn*v2, v2, k2);
    }
    red[t] = (k0 + k1) + k2;
    __syncthreads();
    for (int off = 128; off > 0; off >>= 1) {
        if (t < off) red[t] += red[t + off];
        __syncthreads();
    }
    float pe0 = p_eta[0];
    for (int idx = t; idx < NA*3; idx += 256) {
        int n = idx / 3;
        float mn = mass[n], vv = v[idx];
        out[idx]        = (-g_gq[idx] - pe0 * mn * vv / Q0f) / mn;
        out[NA*3 + idx] = vv;
    }
    if (t == 0) {
        float s_ke = 0.5f * red[0];
        float pe1 = p_eta[1], pe2 = p_eta[2], pe3 = p_eta[3];
        out[2*NA*3 + 0] = 2.0f*(s_ke - TARGETf) - pe0*pe1/QCf;
        out[2*NA*3 + 1] = pe0*pe0/Q0f - KTf - pe1*pe2/QCf;
        out[2*NA*3 + 2] = pe1*pe1/QCf - KTf - pe2*pe3/QCf;
        out[2*NA*3 + 3] = pe2*pe2/QCf - KTf;
    }
}

// ---------------------------------------------------------------------------
extern "C" void kernel_launch(void* const* d_in, const int* in_sizes, int n_in,
                              void* d_out, int out_size) {
    const float* v     = (const float*)d_in[0];
    const float* q     = (const float*)d_in[1];
    const float* p_eta = (const float*)d_in[2];
    const float* mass  = (const float*)d_in[3];
    const float* embed = (const float*)d_in[4];
    const float* W1    = (const float*)d_in[5];
    const float* b1    = (const float*)d_in[6];
    const float* W2    = (const float*)d_in[7];
    const float* b2    = (const float*)d_in[8];
    const float* W3    = (const float*)d_in[9];
    const float* w_out = (const float*)d_in[10];
    const int*   zat   = (const int*)d_in[11];
    float* out = (float*)d_out;
    (void)in_sizes; (void)n_in; (void)out_size;

    const int fwd_smem  = FWD_SMEM_FLOATS  * (int)sizeof(float);  // ~76 KB
    const int bwd_smem  = BWD_SMEM_FLOATS  * (int)sizeof(float);  // ~77 KB
    const int head_smem = HEAD_SMEM_FLOATS * (int)sizeof(float);  // ~137 KB
    cudaFuncSetAttribute(k_fwdP, cudaFuncAttributeMaxDynamicSharedMemorySize, fwd_smem);
    cudaFuncSetAttribute(k_bwdP, cudaFuncAttributeMaxDynamicSharedMemorySize, bwd_smem);
    cudaFuncSetAttribute(k_head, cudaFuncAttributeMaxDynamicSharedMemorySize, head_smem);

    k_prep <<<NA, FDIM>>>(embed, zat);
    k_nbr  <<<NA, 256 >>>(q);
    k_fwdP <<<PGRID, 256, fwd_smem>>>(q, W1, b1, W2, b2);
    k_head <<<96, 256, head_smem>>>(W3, w_out);
    k_bwdP <<<PGRID, 256, bwd_smem>>>(q, W1, W2);
    k_fin  <<<1,  256 >>>(v, mass, p_eta, out);
}